// round 17
// baseline (speedup 1.0000x reference)
#include <cuda_runtime.h>
#include <cuda_fp16.h>
#include <cstdint>

#define N_NODES 8192
#define F_IN    256
#define F_OUT   128
#define KC      32      // j per chunk in attn
#define NCHUNK  64      // 2048 j per CTA / KC
#define LOG2E   1.4426950408889634f

// Named barrier IDs (0 reserved for __syncthreads)
#define FULL0 1
#define FREE0 3

__device__ __half g_hT[F_OUT * N_NODES];        // h^T fp16: [f][j]
__device__ float g_src[N_NODES];                // src * log2e
__device__ float g_dst[N_NODES];                // dst * log2e
__device__ float g_partD[512 * 64 * F_OUT];     // [cta][m][f] partial P@h
__device__ float g_partL[512 * 64];             // [cta][m] partial row sums

__device__ __forceinline__ float ex2(float v) {
    float r;
    asm("ex2.approx.f32 %0, %1;" : "=f"(r) : "f"(v));
    return r;
}
__device__ __forceinline__ uint32_t smem_u32(const void* p) {
    uint32_t a;
    asm("{ .reg .u64 t; cvta.to.shared.u64 t, %1; cvt.u32.u64 %0, t; }" : "=r"(a) : "l"(p));
    return a;
}
__device__ __forceinline__ void cp16(uint32_t dst, const void* src) {
    asm volatile("cp.async.cg.shared.global [%0], [%1], 16;" :: "r"(dst), "l"(src));
}
#define CP_COMMIT() asm volatile("cp.async.commit_group;")
#define CP_WAIT1()  asm volatile("cp.async.wait_group 1;")
#define BAR_SYNC(id)   asm volatile("bar.sync %0, 512;"   :: "r"(id) : "memory")
#define BAR_ARRIVE(id) asm volatile("bar.arrive %0, 512;" :: "r"(id) : "memory")

__device__ __forceinline__ void mma_f16(float* d, const unsigned* a, const unsigned* b) {
    asm volatile(
        "mma.sync.aligned.m16n8k16.row.col.f32.f16.f16.f32 "
        "{%0,%1,%2,%3}, {%4,%5,%6,%7}, {%8,%9}, {%0,%1,%2,%3};\n"
        : "+f"(d[0]), "+f"(d[1]), "+f"(d[2]), "+f"(d[3])
        : "r"(a[0]), "r"(a[1]), "r"(a[2]), "r"(a[3]), "r"(b[0]), "r"(b[1]));
}
__device__ __forceinline__ void ldsm_x4(unsigned* r, uint32_t addr) {
    asm volatile(
        "ldmatrix.sync.aligned.m8n8.x4.shared.b16 {%0,%1,%2,%3}, [%4];"
        : "=r"(r[0]), "=r"(r[1]), "=r"(r[2]), "=r"(r[3]) : "r"(addr));
}
__device__ __forceinline__ void ldsm_x4_tr(unsigned* r, uint32_t addr) {
    asm volatile(
        "ldmatrix.sync.aligned.m8n8.x4.trans.shared.b16 {%0,%1,%2,%3}, [%4];"
        : "=r"(r[0]), "=r"(r[1]), "=r"(r[2]), "=r"(r[3]) : "r"(addr));
}

// ---------------------------------------------------------------------------
// Kernel 1 (tensor-core, 2 CTA/SM): h = fp16MMA(x, W); src/dst EXACT via
// src = x @ (W @ a1). grid 256 (32 rows), block 256.
// smem (bytes): W2 [256 k][136 h] @0 (69632) | x2 [32 m][264 h] @69632 (16896)
//               a_s @86528 (1024) | wa_s @87552 (2048)  -> total 89600
// ---------------------------------------------------------------------------
__global__ void __launch_bounds__(256, 2)
prep_kernel(const float* __restrict__ x, const float* __restrict__ W,
            const float* __restrict__ a) {
    extern __shared__ char smc[];
    const uint32_t sb = smem_u32(smc);
    float* a_s  = (float*)(smc + 86528);
    float* wa_s = (float*)(smc + 87552);        // wa1 [256], wa2 [256]

    const int t = threadIdx.x, lane = t & 31, w = t >> 5;
    const int rbase = blockIdx.x * 32;

    a_s[t] = a[t];
    __syncthreads();

    // ---- Phase 1: W -> W2 fp16 [k][n] (stride 272 B), wa1/wa2 = W @ a ----
    {
        const float4 a1v = *(const float4*)&a_s[4 * lane];
        const float4 a2v = *(const float4*)&a_s[128 + 4 * lane];
        for (int i = 0; i < 32; i++) {
            const int k = w * 32 + i;
            const float4 wv = *(const float4*)&W[k * F_OUT + 4 * lane];
            __half2 h0 = __floats2half2_rn(wv.x, wv.y);
            __half2 h1 = __floats2half2_rn(wv.z, wv.w);
            uint2 u; u.x = *(uint32_t*)&h0; u.y = *(uint32_t*)&h1;
            *(uint2*)(smc + k * 272 + lane * 8) = u;
            float s1 = wv.x * a1v.x + wv.y * a1v.y + wv.z * a1v.z + wv.w * a1v.w;
            float s2 = wv.x * a2v.x + wv.y * a2v.y + wv.z * a2v.z + wv.w * a2v.w;
            #pragma unroll
            for (int o = 16; o; o >>= 1) {
                s1 += __shfl_xor_sync(0xffffffffu, s1, o);
                s2 += __shfl_xor_sync(0xffffffffu, s2, o);
            }
            if (lane == 0) { wa_s[k] = s1; wa_s[256 + k] = s2; }
        }
    }
    __syncthreads();

    // ---- Phase 2: x -> x2 fp16 [m][k] (stride 528 B); src/dst exact ----
    {
        const int m = t >> 3, q = t & 7;        // 32 rows x 8 threads, 32 k each
        const float* xrow = x + (size_t)(rbase + m) * F_IN;
        float sp = 0.f, dp = 0.f;
        #pragma unroll
        for (int i = 0; i < 8; i++) {
            const int k = q * 4 + i * 32;
            const float4 xv = *(const float4*)&xrow[k];
            const float4 w1 = *(const float4*)&wa_s[k];
            const float4 w2 = *(const float4*)&wa_s[256 + k];
            sp += xv.x * w1.x + xv.y * w1.y + xv.z * w1.z + xv.w * w1.w;
            dp += xv.x * w2.x + xv.y * w2.y + xv.z * w2.z + xv.w * w2.w;
            __half2 h0 = __floats2half2_rn(xv.x, xv.y);
            __half2 h1 = __floats2half2_rn(xv.z, xv.w);
            uint2 u; u.x = *(uint32_t*)&h0; u.y = *(uint32_t*)&h1;
            *(uint2*)(smc + 69632 + m * 528 + k * 2) = u;
        }
        #pragma unroll
        for (int o = 4; o; o >>= 1) {
            sp += __shfl_down_sync(0xffffffffu, sp, o, 8);
            dp += __shfl_down_sync(0xffffffffu, dp, o, 8);
        }
        if (q == 0) {
            g_src[rbase + m] = sp * LOG2E;
            g_dst[rbase + m] = dp * LOG2E;
        }
    }
    __syncthreads();

    // ---- Phase 3: MMA  D[32 m][128 f] = x2 @ W2; warp tile 16m x 32f ----
    const int gID = lane >> 2, tig = lane & 3;
    const int oct = lane >> 3, ol = lane & 7;
    const int mw = w & 1, nq = w >> 1;          // 2 m-strips x 4 n-quarters

    const uint32_t a_addr = sb + 69632u
        + (uint32_t)((mw * 16 + (oct & 1) * 8 + ol) * 528 + (oct >> 1) * 16);
    const uint32_t b_addr = sb
        + (uint32_t)(((lane & 7) + ((lane >> 3) & 1) * 8) * 272
                     + (lane >> 4) * 16 + nq * 64);

    float acc[4][4];
    #pragma unroll
    for (int nt = 0; nt < 4; nt++)
        #pragma unroll
        for (int c = 0; c < 4; c++) acc[nt][c] = 0.f;

    #pragma unroll
    for (int ks = 0; ks < 16; ks++) {
        unsigned Af[4];
        ldsm_x4(Af, a_addr + ks * 32);
        #pragma unroll
        for (int j = 0; j < 2; j++) {
            unsigned Bf[4];
            ldsm_x4_tr(Bf, b_addr + ks * 16 * 272 + j * 32);
            mma_f16(acc[2 * j],     Af, Bf);
            mma_f16(acc[2 * j + 1], Af, Bf + 2);
        }
    }
    __syncthreads();    // all x2 reads done; safe to overwrite as hT_tile

    // ---- Phase 4: transpose D -> hT_tile [128 f][40 m], coalesced out ----
    __half* hT = (__half*)(smc + 69632);
    {
        const int m = mw * 16 + gID;
        #pragma unroll
        for (int nt = 0; nt < 4; nt++) {
            const int f = nq * 32 + nt * 8 + 2 * tig;
            hT[f * 40 + m]           = __float2half_rn(acc[nt][0]);
            hT[(f + 1) * 40 + m]     = __float2half_rn(acc[nt][1]);
            hT[f * 40 + m + 8]       = __float2half_rn(acc[nt][2]);
            hT[(f + 1) * 40 + m + 8] = __float2half_rn(acc[nt][3]);
        }
    }
    __syncthreads();
    #pragma unroll
    for (int i = 0; i < 2; i++) {
        const int idx = t + i * 256;            // 512 float4 total
        const int f = idx >> 2, seg = idx & 3;
        float4 v = *(const float4*)&hT[f * 40 + seg * 8];
        *(float4*)&g_hT[(size_t)f * N_NODES + rbase + seg * 8] = v;
    }
}

// ---------------------------------------------------------------------------
// Kernel 2: warp-specialized fused masked-softmax attention (R13-exact).
// grid 512: rb = bid>>2 (64 rows), jq = bid&3 (2048 j). block 512, 2 CTAs/SM.
// ---------------------------------------------------------------------------
__global__ void __launch_bounds__(512, 2)
attn_kernel(const int* __restrict__ adj) {
    extern __shared__ float sm[];
    __half2* P2_s = (__half2*)(sm + 7680);
    float*   dst_s = sm + 10240;
    const uint32_t h_u = smem_u32(sm);          // byte address of h stage 0
    const uint32_t P_u = h_u + 7680 * 4;        // byte address of P buf 0

    const int t    = threadIdx.x;
    const int rb   = blockIdx.x >> 2, jq = blockIdx.x & 3;
    const int r0   = rb * 64;
    const int jbase = jq * 2048;
    const int w    = t >> 5;

    *(float4*)&dst_s[t * 4] = *(const float4*)&g_dst[jbase + t * 4];
    __syncthreads();

    if (w < 8) {
        // ================= PRODUCER =================
        const int row = t >> 2, q = t & 3;
        const int* asrc = adj + (size_t)(r0 + row) * N_NODES + jbase + q * 8;
        const float srcv = g_src[r0 + row] - 4.0f;
        float l_reg = 0.f;

        int4 adjv[2][2];
        #pragma unroll
        for (int s = 0; s < 2; s++) {
            adjv[s][0] = *(const int4*)(asrc + s * KC);
            adjv[s][1] = *(const int4*)(asrc + s * KC + 4);
        }

        #pragma unroll 2
        for (int ch = 0; ch < NCHUNK; ch++) {
            const int slot = ch & 1;
            if (ch >= 2) BAR_SYNC(FREE0 + slot);

            __half2* Pb = P2_s + slot * 1280;
            float lsum = 0.f;
            uint4 pk;
            #pragma unroll
            for (int i = 0; i < 2; i++) {
                const int4 av = adjv[slot][i];
                const float4 dv = *(const float4*)&dst_s[ch * KC + q * 8 + i * 4];
                float s0, s1, s2, s3;
                s0 = srcv + dv.x; s0 = fmaxf(s0, 0.2f * s0 - 3.2f);
                s1 = srcv + dv.y; s1 = fmaxf(s1, 0.2f * s1 - 3.2f);
                s2 = srcv + dv.z; s2 = fmaxf(s2, 0.2f * s2 - 3.2f);
                s3 = srcv + dv.w; s3 = fmaxf(s3, 0.2f * s3 - 3.2f);
                float p0 = (av.x > 0) ? ex2(s0) : 0.f;
                float p1 = (av.y > 0) ? ex2(s1) : 0.f;
                float p2 = (av.z > 0) ? ex2(s2) : 0.f;
                float p3 = (av.w > 0) ? ex2(s3) : 0.f;
                lsum += (p0 + p1) + (p2 + p3);
                __half2 h01 = __floats2half2_rn(p0, p1);
                __half2 h23 = __floats2half2_rn(p2, p3);
                if (i == 0) { pk.x = *(uint32_t*)&h01; pk.y = *(uint32_t*)&h23; }
                else        { pk.z = *(uint32_t*)&h01; pk.w = *(uint32_t*)&h23; }
            }
            *(uint4*)&Pb[row * 20 + q * 4] = pk;

            BAR_ARRIVE(FULL0 + slot);

            if (ch + 2 < NCHUNK) {
                adjv[slot][0] = *(const int4*)(asrc + (ch + 2) * KC);
                adjv[slot][1] = *(const int4*)(asrc + (ch + 2) * KC + 4);
            }
            lsum += __shfl_xor_sync(0xffffffffu, lsum, 1, 4);
            lsum += __shfl_xor_sync(0xffffffffu, lsum, 2, 4);
            if (q == 0) l_reg += lsum;
        }
        if (q == 0) g_partL[blockIdx.x * 64 + row] = l_reg;

    } else {
        // ================= CONSUMER =================
        const int tc   = t - 256;
        const int lane = t & 31, wc = w - 8;
        const int gID  = lane >> 2, tig = lane & 3;
        const int mh   = wc & 1;
        const int nq   = wc >> 1;
        const int oct  = lane >> 3, ol = lane & 7;

        const uint32_t a_lane = (uint32_t)((mh * 32 + ((oct & 1) << 3) + ol) * 80
                                           + ((oct >> 1) << 4));
        const uint32_t b_lane = (uint32_t)((nq * 32 + ((oct >> 1) << 3) + ol) * 80
                                           + ((oct & 1) << 4));

        float acc[2][4][4];
        #pragma unroll
        for (int mt = 0; mt < 2; mt++)
            #pragma unroll
            for (int nt = 0; nt < 4; nt++)
                #pragma unroll
                for (int c = 0; c < 4; c++) acc[mt][nt][c] = 0.f;

        const int hn = tc >> 1, hseg = tc & 1;
        const __half* hsrc = g_hT + (size_t)hn * N_NODES + jbase + hseg * 16;
        const uint32_t hdst = h_u + (hn * 20 + hseg * 8) * 4;

        #define ISSUE_H(ch_, stoff_)                                   \
        {                                                              \
            cp16(hdst + (stoff_), hsrc + (ch_) * KC);                  \
            cp16(hdst + (stoff_) + 16, hsrc + (ch_) * KC + 8);         \
        }

        ISSUE_H(0, 0);        CP_COMMIT();
        ISSUE_H(1, 2560 * 4); CP_COMMIT();

        int st = 0;
        #pragma unroll 2
        for (int ch = 0; ch < NCHUNK; ch++) {
            const int slot = ch & 1;
            CP_WAIT1();
            BAR_SYNC(FULL0 + slot);

            if (ch + 2 < NCHUNK) {
                const int stn = (st + 2 >= 3) ? st - 1 : st + 2;
                ISSUE_H(ch + 2, stn * 2560 * 4);
            }
            CP_COMMIT();

            const uint32_t Pa = P_u + slot * 5120 + a_lane;
            const uint32_t Ha = h_u + st * 10240 + b_lane;
            #pragma unroll
            for (int ks = 0; ks < 2; ks++) {
                unsigned Af[2][4];
                ldsm_x4(Af[0], Pa + ks * 32);
                ldsm_x4(Af[1], Pa + ks * 32 + 16 * 80);
                #pragma unroll
                for (int n2 = 0; n2 < 2; n2++) {
                    unsigned Bf[4];
                    ldsm_x4(Bf, Ha + ks * 32 + n2 * 16 * 80);
                    mma_f16(acc[0][2 * n2],     Af[0], Bf);
                    mma_f16(acc[0][2 * n2 + 1], Af[0], Bf + 2);
                    mma_f16(acc[1][2 * n2],     Af[1], Bf);
                    mma_f16(acc[1][2 * n2 + 1], Af[1], Bf + 2);
                }
            }

            if (ch + 2 < NCHUNK) BAR_ARRIVE(FREE0 + slot);
            st = (st + 1 >= 3) ? 0 : st + 1;
        }

        const size_t dbase = (size_t)blockIdx.x * 64 * F_OUT;
        #pragma unroll
        for (int mt = 0; mt < 2; mt++) {
            const int ra = mh * 32 + mt * 16 + gID;
            #pragma unroll
            for (int nt = 0; nt < 4; nt++) {
                const int c = nq * 32 + nt * 8 + 2 * tig;
                float2 v0, v1;
                v0.x = acc[mt][nt][0]; v0.y = acc[mt][nt][1];
                v1.x = acc[mt][nt][2]; v1.y = acc[mt][nt][3];
                *(float2*)&g_partD[dbase + (size_t)ra * F_OUT + c]       = v0;
                *(float2*)&g_partD[dbase + (size_t)(ra + 8) * F_OUT + c] = v1;
            }
        }
    }
}

// ---------------------------------------------------------------------------
// Kernel 3: combine 4 j-quarters: out = sum(D_p) / sum(l_p)
// ---------------------------------------------------------------------------
__global__ void __launch_bounds__(512, 4)
combine_kernel(float* __restrict__ out) {
    const int idx  = blockIdx.x * 512 + threadIdx.x;
    const int rowc = idx >> 5;
    const int c4   = idx & 31;
    const int rbk  = rowc >> 6, m = rowc & 63;
    const size_t b0 = (size_t)(4 * rbk) * 64 * F_OUT + (size_t)m * F_OUT + c4 * 4;
    const float4 d0 = *(const float4*)&g_partD[b0];
    const float4 d1 = *(const float4*)&g_partD[b0 + 1 * 64 * F_OUT];
    const float4 d2 = *(const float4*)&g_partD[b0 + 2 * 64 * F_OUT];
    const float4 d3 = *(const float4*)&g_partD[b0 + 3 * 64 * F_OUT];
    const float lsum = g_partL[(4 * rbk + 0) * 64 + m] + g_partL[(4 * rbk + 1) * 64 + m]
                     + g_partL[(4 * rbk + 2) * 64 + m] + g_partL[(4 * rbk + 3) * 64 + m];
    const float inv = 1.f / lsum;
    float4 o;
    o.x = ((d0.x + d1.x) + (d2.x + d3.x)) * inv;
    o.y = ((d0.y + d1.y) + (d2.y + d3.y)) * inv;
    o.z = ((d0.z + d1.z) + (d2.z + d3.z)) * inv;
    o.w = ((d0.w + d1.w) + (d2.w + d3.w)) * inv;
    *(float4*)&out[(size_t)rowc * F_OUT + c4 * 4] = o;
}

// ---------------------------------------------------------------------------
extern "C" void kernel_launch(void* const* d_in, const int* in_sizes, int n_in,
                              void* d_out, int out_size) {
    const float* x   = (const float*)d_in[0];
    const int*   adj = (const int*)  d_in[1];
    const float* W   = (const float*)d_in[2];
    const float* a   = (const float*)d_in[3];
    float* out = (float*)d_out;

    const int A_SMEM = 89600;                                   // 87.5 KB
    const int B_SMEM = 12288 * 4;                               // 48 KB
    cudaFuncSetAttribute(prep_kernel, cudaFuncAttributeMaxDynamicSharedMemorySize, A_SMEM);
    cudaFuncSetAttribute(attn_kernel, cudaFuncAttributeMaxDynamicSharedMemorySize, B_SMEM);

    prep_kernel<<<256, 256, A_SMEM>>>(x, W, a);
    attn_kernel<<<512, 512, B_SMEM>>>(adj);
    combine_kernel<<<512, 512>>>(out);
}